// round 12
// baseline (speedup 1.0000x reference)
#include <cuda_runtime.h>
#include <cuda_bf16.h>
#include <cstdint>

#define NTOK   4096
#define NV     204
#define NH     128
#define NH2    256

// ------------------------------------------------------------------
// Device scratch (zero-init, no allocations)
// ------------------------------------------------------------------
// Combined weight Wc[v] in FRAGMENT-MAJOR layout (16384 u32 words per v):
// word index = ((kk*16 + half*8 + which*4 + s4)*128) + lane*4 + sj
//   kk = k-block (0..7), half = fc/gate, which = b0/b1 octet,
//   s = 4*s4+sj = n-tile (0..15), lane = 4*g + tig (mma thread id)
// word packs bf16(h=2k2) | bf16(h=2k2+1)<<16 with k2 = 8kk + 4which + tig.
__device__ __nv_bfloat16 g_bhi[(size_t)NV * 32768];
__device__ __nv_bfloat16 g_blo[(size_t)NV * 32768];
__device__ float g_bc[NV * 256];
__device__ float g_vpart[(size_t)NV * NTOK * NH];
__device__ float g_wtsT[NV * NTOK];

typedef unsigned long long ull;
typedef uint32_t u32;

__device__ __forceinline__ void ffma2(ull &d, ull a, ull b) {
    asm("fma.rn.f32x2 %0, %1, %2, %0;" : "+l"(d) : "l"(a), "l"(b));
}
__device__ __forceinline__ float upk_sum(ull v) {
    float lo, hi;
    asm("mov.b64 {%0, %1}, %2;" : "=f"(lo), "=f"(hi) : "l"(v));
    return lo + hi;
}
__device__ __forceinline__ float warp_sum(float s) {
    #pragma unroll
    for (int o = 16; o > 0; o >>= 1) s += __shfl_xor_sync(0xffffffffu, s, o);
    return s;
}
__device__ __forceinline__ float warp_max(float s) {
    #pragma unroll
    for (int o = 16; o > 0; o >>= 1) s = fmaxf(s, __shfl_xor_sync(0xffffffffu, s, o));
    return s;
}
__device__ __forceinline__ float elu1(float t) { return t > 0.f ? t : expm1f(t); }
__device__ __forceinline__ float elu1f(float t) { return t > 0.f ? t : __expf(t) - 1.f; }

__device__ __forceinline__ void mma16816(float* d, u32 a0, u32 a1, u32 a2, u32 a3,
                                         u32 b0, u32 b1) {
    asm volatile("mma.sync.aligned.m16n8k16.row.col.f32.bf16.bf16.f32 "
        "{%0,%1,%2,%3}, {%4,%5,%6,%7}, {%8,%9}, {%0,%1,%2,%3};"
        : "+f"(d[0]), "+f"(d[1]), "+f"(d[2]), "+f"(d[3])
        : "r"(a0), "r"(a1), "r"(a2), "r"(a3), "r"(b0), "r"(b1));
}
__device__ __forceinline__ void split2(float t0, float t1, u32 &wh, u32 &wl) {
    __nv_bfloat16 h0 = __float2bfloat16(t0);
    __nv_bfloat16 l0 = __float2bfloat16(t0 - __bfloat162float(h0));
    __nv_bfloat16 h1 = __float2bfloat16(t1);
    __nv_bfloat16 l1 = __float2bfloat16(t1 - __bfloat162float(h1));
    wh = (u32)__bfloat16_as_ushort(h0) | ((u32)__bfloat16_as_ushort(h1) << 16);
    wl = (u32)__bfloat16_as_ushort(l0) | ((u32)__bfloat16_as_ushort(l1) << 16);
}

// ------------------------------------------------------------------
// Prepass: Wc[v] = fc2_w[v] @ glu_w[v]^T (fp32), emit fragment-major
// bf16 hi/lo.  bc[v] = fc2_b[v] @ glu_w[v]^T + glu_b[v]
// ------------------------------------------------------------------
#define PREP_SA    0
#define PREP_SB    66560
#define PREP_F2B   83200
#define PREP_SMEM  83712

__global__ __launch_bounds__(256) void prep_wc(
    const float* __restrict__ fc2_w, const float* __restrict__ fc2_b,
    const float* __restrict__ glu_w, const float* __restrict__ glu_b)
{
    extern __shared__ char smraw[];
    float* sA   = (float*)(smraw + PREP_SA);
    float* sB   = (float*)(smraw + PREP_SB);
    float* sf2b = (float*)(smraw + PREP_F2B);

    const int tid = threadIdx.x;
    const int v   = blockIdx.x;

    for (int i = tid; i < 16384; i += 256) {
        int h = i >> 7, k = i & 127;
        sA[h * 130 + k] = fc2_w[(size_t)v * 16384 + i];
    }
    if (tid < 128) sf2b[tid] = fc2_b[v * NH + tid];
    __syncthreads();

    const int h  = tid & 127;    // contract-dim index of Wc row
    const int g0 = (tid >> 7) * 16;

    // fragment-coord pieces for this h
    const int k2    = h >> 1;
    const int hw    = h & 1;
    const int tig   = k2 & 3;
    const int which = (k2 >> 2) & 1;
    const int kk    = k2 >> 3;

    for (int gt = 0; gt < 8; gt++) {
        for (int i = tid; i < 4096; i += 256) {
            int g = i >> 7, k = i & 127;
            sB[g * 130 + k] = glu_w[(size_t)v * 32768 + gt * 4096 + i];
        }
        __syncthreads();

        ull acc[16];
        #pragma unroll
        for (int j = 0; j < 16; j++) acc[j] = 0ull;

        #pragma unroll 4
        for (int kp = 0; kp < 64; kp++) {
            ull a = *(const ull*)(sA + h * 130 + 2 * kp);
            #pragma unroll
            for (int j = 0; j < 16; j++)
                ffma2(acc[j], a, *(const ull*)(sB + (g0 + j) * 130 + 2 * kp));
        }
        #pragma unroll
        for (int j = 0; j < 16; j++) {
            int gabs = gt * 32 + g0 + j;
            float val = upk_sum(acc[j]);
            __nv_bfloat16 hi = __float2bfloat16(val);
            __nv_bfloat16 lo = __float2bfloat16(val - __bfloat162float(hi));
            int halfc = gabs >> 7;
            int rem   = gabs & 127;
            int gg    = rem & 7;
            int s     = rem >> 3;
            int s4    = s >> 2, sj = s & 3;
            int lanec = 4 * gg + tig;
            int bfw   = ((kk * 16 + halfc * 8 + which * 4 + s4) * 128) + lanec * 4 + sj;
            size_t bi = (size_t)v * 32768 + (size_t)bfw * 2 + hw;
            g_bhi[bi] = hi;
            g_blo[bi] = lo;
        }
        if (tid < 32) {
            float s = 0.f;
            for (int k = 0; k < 128; k++) s += sf2b[k] * sB[tid * 130 + k];
            g_bc[v * 256 + gt * 32 + tid] = s + glu_b[(size_t)v * 256 + gt * 32 + tid];
        }
        __syncthreads();
    }
}

// ------------------------------------------------------------------
// Kernel 1: weights branch -> softmax wts (unchanged, known-correct)
// ------------------------------------------------------------------
__global__ __launch_bounds__(256) void wts_kernel(
    const float* __restrict__ x,
    const float* __restrict__ wfc1_w, const float* __restrict__ wfc1_b,
    const float* __restrict__ wfc2_w, const float* __restrict__ wfc2_b,
    const float* __restrict__ wglu_w, const float* __restrict__ wglu_b,
    const float* __restrict__ wln_g,  const float* __restrict__ wln_b,
    float* __restrict__ wts_out)
{
    __shared__ float sx[8][NV];
    __shared__ float sa[8][NH];
    __shared__ float sb[8][NH];
    __shared__ float sg[8][2 * NV];

    const int tid = threadIdx.x;
    const int n0  = blockIdx.x * 8;

    for (int i = tid; i < 8 * NV; i += 256) sx[i / NV][i % NV] = x[n0 * NV + i];
    __syncthreads();

    const int h  = tid & 127;
    const int rh = tid >> 7;

    {
        float acc[4];
        float bia = wfc1_b[h];
        #pragma unroll
        for (int i = 0; i < 4; i++) acc[i] = bia;
        for (int v = 0; v < NV; v++) {
            float w = wfc1_w[v * NH + h];
            #pragma unroll
            for (int i = 0; i < 4; i++) acc[i] += sx[rh * 4 + i][v] * w;
        }
        #pragma unroll
        for (int i = 0; i < 4; i++) sa[rh * 4 + i][h] = elu1(acc[i]);
    }
    __syncthreads();

    {
        float acc[4];
        float bia = wfc2_b[h];
        #pragma unroll
        for (int i = 0; i < 4; i++) acc[i] = bia;
        for (int k = 0; k < NH; k++) {
            float w = wfc2_w[k * NH + h];
            #pragma unroll
            for (int i = 0; i < 4; i++) acc[i] += sa[rh * 4 + i][k] * w;
        }
        #pragma unroll
        for (int i = 0; i < 4; i++) sb[rh * 4 + i][h] = acc[i];
    }
    __syncthreads();

    for (int jb = 0; jb < 2 * NV; jb += 256) {
        int j = jb + tid;
        if (j < 2 * NV) {
            float acc[8];
            float bia = wglu_b[j];
            #pragma unroll
            for (int r = 0; r < 8; r++) acc[r] = bia;
            for (int k = 0; k < NH; k++) {
                float w = wglu_w[k * 2 * NV + j];
                #pragma unroll
                for (int r = 0; r < 8; r++) acc[r] += sb[r][k] * w;
            }
            #pragma unroll
            for (int r = 0; r < 8; r++) sg[r][j] = acc[r];
        }
    }
    __syncthreads();

    const int r = tid >> 5, l = tid & 31;
    float y[7];
    #pragma unroll
    for (int p = 0; p < 7; p++) {
        int v = l + 32 * p;
        if (v < NV) {
            float fo  = sg[r][v];
            float gt  = sg[r][v + NV];
            float sig = 1.f / (1.f + expf(-gt));
            y[p] = sx[r][v] + fo * sig;
        } else y[p] = 0.f;
    }
    float s = 0.f;
    #pragma unroll
    for (int p = 0; p < 7; p++) s += y[p];
    float mean = warp_sum(s) * (1.f / (float)NV);

    float s2 = 0.f;
    #pragma unroll
    for (int p = 0; p < 7; p++) {
        int v = l + 32 * p;
        if (v < NV) { float d = y[p] - mean; s2 += d * d; }
    }
    float rs = rsqrtf(warp_sum(s2) * (1.f / (float)NV) + 1e-5f);

    float z[7]; float zmax = -1e30f;
    #pragma unroll
    for (int p = 0; p < 7; p++) {
        int v = l + 32 * p;
        if (v < NV) {
            z[p] = (y[p] - mean) * rs * wln_g[v] + wln_b[v];
            zmax = fmaxf(zmax, z[p]);
        } else z[p] = -1e30f;
    }
    zmax = warp_max(zmax);
    float es = 0.f;
    #pragma unroll
    for (int p = 0; p < 7; p++) {
        int v = l + 32 * p;
        if (v < NV) { z[p] = expf(z[p] - zmax); es += z[p]; }
    }
    float inv = 1.f / warp_sum(es);
    #pragma unroll
    for (int p = 0; p < 7; p++) {
        int v = l + 32 * p;
        if (v < NV) {
            float wt = z[p] * inv;
            wts_out[(n0 + r) * NV + v] = wt;
            g_wtsT[v * NTOK + n0 + r]  = wt;
        }
    }
}

// ------------------------------------------------------------------
// Main kernel: HMMA bf16 3-term GEMM, fragment-major B (LDS.128),
// A in [row][kk][tig][which] layout (LDS.64), all-warp epilogue.
// ------------------------------------------------------------------
#define SB_BFH  0                  // 65536 B
#define SB_BFL  65536              // 65536 B -> 131072
#define SB_AH   131072             // 64*72*4 = 18432
#define SB_AL   149504             // 18432 -> 167936
#define SB_FCB  131072             // fc preact 64*132*4 = 33792 (overlays AH/AL)
#define SB_GTB  167936             // gate preact 33792 -> 201728
#define SB_SX   201728
#define SB_SWT  201984
#define SB_F1W  202240
#define SB_F1B  202752
#define SB_SKW  203264
#define SB_SKB  203776
#define SB_LNG  204288
#define SB_LNB  204800
#define SB_BC   205312             // 256 f32 -> 206336
#define SB_SMEM 206336

__global__ __launch_bounds__(256, 1) void mma_main(
    const float* __restrict__ x,
    const float* __restrict__ fc1_w, const float* __restrict__ fc1_b,
    const float* __restrict__ skip_w, const float* __restrict__ skip_b,
    const float* __restrict__ ln_g,  const float* __restrict__ ln_b)
{
    extern __shared__ char smraw[];
    u32*   BFH  = (u32*)(smraw + SB_BFH);
    u32*   BFL  = (u32*)(smraw + SB_BFL);
    u32*   AH   = (u32*)(smraw + SB_AH);
    u32*   AL   = (u32*)(smraw + SB_AL);
    float* fcb  = (float*)(smraw + SB_FCB);
    float* gtb  = (float*)(smraw + SB_GTB);
    float* sx   = (float*)(smraw + SB_SX);
    float* swt  = (float*)(smraw + SB_SWT);
    float* sf1w = (float*)(smraw + SB_F1W);
    float* sf1b = (float*)(smraw + SB_F1B);
    float* sskw = (float*)(smraw + SB_SKW);
    float* sskb = (float*)(smraw + SB_SKB);
    float* slng = (float*)(smraw + SB_LNG);
    float* slnb = (float*)(smraw + SB_LNB);
    float* sbc  = (float*)(smraw + SB_BC);

    const int tid  = threadIdx.x;
    const int wid  = tid >> 5;
    const int lane = tid & 31;
    const int g    = lane >> 2;
    const int tig  = lane & 3;
    const int half = wid >> 2;       // 0 = fc cols, 1 = gate cols
    const int w2   = wid & 3;
    const int r0   = 16 * w2;
    const int v    = blockIdx.y;

    // copy fragment-major Wc slabs (65536 B each)
    {
        const int4* srcH = (const int4*)(g_bhi + (size_t)v * 32768);
        const int4* srcL = (const int4*)(g_blo + (size_t)v * 32768);
        int4* dH = (int4*)BFH;
        int4* dL = (int4*)BFL;
        for (int i = tid; i < 4096; i += 256) { dH[i] = srcH[i]; dL[i] = srcL[i]; }
    }
    if (tid < 128) {
        sf1w[tid] = fc1_w[v * NH + tid];
        sf1b[tid] = fc1_b[v * NH + tid];
        sskw[tid] = skip_w[v * NH + tid];
        sskb[tid] = skip_b[v * NH + tid];
        slng[tid] = ln_g[tid];
        slnb[tid] = ln_b[tid];
    }
    sbc[tid] = g_bc[v * 256 + tid];

    const int arow0 = (r0 + g) * 72;
    const int arow1 = (r0 + g + 8) * 72;

    for (int mi = 0; mi < 8; mi++) {
        const int n0 = (blockIdx.x * 8 + mi) * 64;
        __syncthreads();   // prev epilogue readers done; B copy done (mi=0)

        if (tid < 64) {
            sx[tid]  = x[(size_t)(n0 + tid) * NV + v];
            swt[tid] = g_wtsT[v * NTOK + n0 + tid];
        }
        // A staging: [row][kk][tig][which] with row stride 72
        for (int idx = tid; idx < 4096; idx += 256) {
            int row = idx >> 6, k2 = idx & 63;
            float xv = x[(size_t)(n0 + row) * NV + v];
            float t0 = elu1f(xv * sf1w[2 * k2]     + sf1b[2 * k2]);
            float t1 = elu1f(xv * sf1w[2 * k2 + 1] + sf1b[2 * k2 + 1]);
            u32 wh, wl;
            split2(t0, t1, wh, wl);
            int aoff = row * 72 + (k2 >> 3) * 8 + (k2 & 3) * 2 + ((k2 >> 2) & 1);
            AH[aoff] = wh;
            AL[aoff] = wl;
        }
        __syncthreads();

        float acc[16][4];
        #pragma unroll
        for (int s = 0; s < 16; s++)
            #pragma unroll
            for (int j = 0; j < 4; j++) acc[s][j] = 0.f;

        for (int kk = 0; kk < 8; kk++) {
            const int aoff = kk * 8 + tig * 2;
            uint2 xh0 = *(const uint2*)(AH + arow0 + aoff);   // (row0 w0, row0 w1)
            uint2 xh1 = *(const uint2*)(AH + arow1 + aoff);
            uint2 xl0 = *(const uint2*)(AL + arow0 + aoff);
            uint2 xl1 = *(const uint2*)(AL + arow1 + aoff);

            u32 bh[32];
            const u32* pbh = BFH + (kk * 16 + half * 8) * 128 + lane * 4;
            #pragma unroll
            for (int q = 0; q < 8; q++)
                *(uint4*)(bh + 4 * q) = *(const uint4*)(pbh + q * 128);
            #pragma unroll
            for (int s = 0; s < 16; s++)
                mma16816(acc[s], xh0.x, xh1.x, xh0.y, xh1.y, bh[s], bh[16 + s]);

            u32 bl[32];
            const u32* pbl = BFL + (kk * 16 + half * 8) * 128 + lane * 4;
            #pragma unroll
            for (int q = 0; q < 8; q++)
                *(uint4*)(bl + 4 * q) = *(const uint4*)(pbl + q * 128);
            #pragma unroll
            for (int s = 0; s < 16; s++)
                mma16816(acc[s], xh0.x, xh1.x, xh0.y, xh1.y, bl[s], bl[16 + s]);
            #pragma unroll
            for (int s = 0; s < 16; s++)
                mma16816(acc[s], xl0.x, xl1.x, xl0.y, xl1.y, bh[s], bh[16 + s]);
        }
        __syncthreads();   // all MMA reads of AH/AL done before overlay write

        // publish biased preacts (fc warps -> fcb, gate -> gtb)
        {
            float* pre = half ? gtb : fcb;
            const float* bias = sbc + half * 128;
            #pragma unroll
            for (int s = 0; s < 16; s++)
                #pragma unroll
                for (int j = 0; j < 4; j++) {
                    int cg  = 8 * s + 2 * tig + (j & 1);
                    int row = r0 + g + 8 * (j >> 1);
                    pre[row * 132 + cg] = acc[s][j] + bias[cg];
                }
        }
        __syncthreads();

        // all-warp epilogue: warp w handles rows 8w..8w+7
        {
            float lngv0 = slng[4 * lane],     lngv1 = slng[4 * lane + 1];
            float lngv2 = slng[4 * lane + 2], lngv3 = slng[4 * lane + 3];
            float lnbv0 = slnb[4 * lane],     lnbv1 = slnb[4 * lane + 1];
            float lnbv2 = slnb[4 * lane + 2], lnbv3 = slnb[4 * lane + 3];
            float skw0 = sskw[4 * lane],     skw1 = sskw[4 * lane + 1];
            float skw2 = sskw[4 * lane + 2], skw3 = sskw[4 * lane + 3];
            float skb0 = sskb[4 * lane],     skb1 = sskb[4 * lane + 1];
            float skb2 = sskb[4 * lane + 2], skb3 = sskb[4 * lane + 3];

            #pragma unroll
            for (int rr = 0; rr < 8; rr++) {
                int row = 8 * wid + rr;
                float4 f  = *(const float4*)(fcb + row * 132 + 4 * lane);
                float4 gt = *(const float4*)(gtb + row * 132 + 4 * lane);
                float xv  = sx[row];
                float wt  = swt[row];
                float val0 = f.x * (1.f / (1.f + __expf(-gt.x))) + xv * skw0 + skb0;
                float val1 = f.y * (1.f / (1.f + __expf(-gt.y))) + xv * skw1 + skb1;
                float val2 = f.z * (1.f / (1.f + __expf(-gt.z))) + xv * skw2 + skb2;
                float val3 = f.w * (1.f / (1.f + __expf(-gt.w))) + xv * skw3 + skb3;
                float mean = warp_sum(val0 + val1 + val2 + val3) * (1.f / 128.f);
                float d0 = val0 - mean, d1 = val1 - mean, d2 = val2 - mean, d3 = val3 - mean;
                float rs = rsqrtf(warp_sum(d0 * d0 + d1 * d1 + d2 * d2 + d3 * d3) * (1.f / 128.f) + 1e-5f);
                float4 o;
                o.x = wt * (d0 * rs * lngv0 + lnbv0);
                o.y = wt * (d1 * rs * lngv1 + lnbv1);
                o.z = wt * (d2 * rs * lngv2 + lnbv2);
                o.w = wt * (d3 * rs * lngv3 + lnbv3);
                *(float4*)(g_vpart + (size_t)v * ((size_t)NTOK * NH)
                           + (size_t)(n0 + row) * NH + 4 * lane) = o;
            }
        }
    }
}

// ------------------------------------------------------------------
// Reduce: sum 204 per-variable partials -> out
// ------------------------------------------------------------------
__global__ __launch_bounds__(256) void reduce_kernel(float* __restrict__ out)
{
    int i = blockIdx.x * 256 + threadIdx.x;
    const float* p = g_vpart + i;
    float s = 0.f;
    #pragma unroll 4
    for (int v = 0; v < NV; v++) s += p[(size_t)v * ((size_t)NTOK * NH)];
    out[i] = s;
}

// ------------------------------------------------------------------
extern "C" void kernel_launch(void* const* d_in, const int* in_sizes, int n_in,
                              void* d_out, int out_size) {
    const float* x      = (const float*)d_in[0];
    const float* fc1_w  = (const float*)d_in[1];
    const float* fc1_b  = (const float*)d_in[2];
    const float* fc2_w  = (const float*)d_in[3];
    const float* fc2_b  = (const float*)d_in[4];
    const float* glu_w  = (const float*)d_in[5];
    const float* glu_b  = (const float*)d_in[6];
    const float* skip_w = (const float*)d_in[7];
    const float* skip_b = (const float*)d_in[8];
    const float* ln_g   = (const float*)d_in[9];
    const float* ln_b   = (const float*)d_in[10];
    const float* wfc1_w = (const float*)d_in[11];
    const float* wfc1_b = (const float*)d_in[12];
    const float* wfc2_w = (const float*)d_in[13];
    const float* wfc2_b = (const float*)d_in[14];
    const float* wglu_w = (const float*)d_in[15];
    const float* wglu_b = (const float*)d_in[16];
    const float* wln_g  = (const float*)d_in[17];
    const float* wln_b  = (const float*)d_in[18];

    float* out = (float*)d_out;
    float* wts = out + (size_t)NTOK * NH;

    cudaFuncSetAttribute(prep_wc,  cudaFuncAttributeMaxDynamicSharedMemorySize, PREP_SMEM);
    cudaFuncSetAttribute(mma_main, cudaFuncAttributeMaxDynamicSharedMemorySize, SB_SMEM);

    prep_wc<<<NV, 256, PREP_SMEM>>>(fc2_w, fc2_b, glu_w, glu_b);
    wts_kernel<<<NTOK / 8, 256>>>(x, wfc1_w, wfc1_b, wfc2_w, wfc2_b,
                                  wglu_w, wglu_b, wln_g, wln_b, wts);
    mma_main<<<dim3(8, NV), 256, SB_SMEM>>>(
        x, fc1_w, fc1_b, skip_w, skip_b, ln_g, ln_b);
    reduce_kernel<<<(NTOK * NH) / 256, 256>>>(out);
}

// round 13
// speedup vs baseline: 1.1144x; 1.1144x over previous
#include <cuda_runtime.h>
#include <cuda_bf16.h>
#include <cuda_fp16.h>
#include <cstdint>

#define NTOK   4096
#define NV     204
#define NH     128
#define NH2    256

// ------------------------------------------------------------------
// Device scratch (zero-init, no allocations)
// ------------------------------------------------------------------
// Combined weight Wc[v] as SINGLE fp16, fragment-major (16384 u32 words/v):
// word index = ((kk*16 + half*8 + which*4 + s4)*128) + lane*4 + sj
// word packs fp16(h=2k2) | fp16(h=2k2+1)<<16 with k2 = 8kk + 4which + tig.
__device__ __half g_bf[(size_t)NV * 32768];
__device__ float g_bc[NV * 256];
__device__ float g_vpart[(size_t)NV * NTOK * NH];
__device__ float g_wtsT[NV * NTOK];

typedef unsigned long long ull;
typedef uint32_t u32;

__device__ __forceinline__ void ffma2(ull &d, ull a, ull b) {
    asm("fma.rn.f32x2 %0, %1, %2, %0;" : "+l"(d) : "l"(a), "l"(b));
}
__device__ __forceinline__ float upk_sum(ull v) {
    float lo, hi;
    asm("mov.b64 {%0, %1}, %2;" : "=f"(lo), "=f"(hi) : "l"(v));
    return lo + hi;
}
__device__ __forceinline__ float warp_sum(float s) {
    #pragma unroll
    for (int o = 16; o > 0; o >>= 1) s += __shfl_xor_sync(0xffffffffu, s, o);
    return s;
}
__device__ __forceinline__ float warp_max(float s) {
    #pragma unroll
    for (int o = 16; o > 0; o >>= 1) s = fmaxf(s, __shfl_xor_sync(0xffffffffu, s, o));
    return s;
}
__device__ __forceinline__ float elu1(float t) { return t > 0.f ? t : expm1f(t); }
__device__ __forceinline__ float elu1f(float t) { return t > 0.f ? t : __expf(t) - 1.f; }

// fp16 HMMA m16n8k16, fp32 accumulate
__device__ __forceinline__ void mma16816h(float* d, u32 a0, u32 a1, u32 a2, u32 a3,
                                          u32 b0, u32 b1) {
    asm volatile("mma.sync.aligned.m16n8k16.row.col.f32.f16.f16.f32 "
        "{%0,%1,%2,%3}, {%4,%5,%6,%7}, {%8,%9}, {%0,%1,%2,%3};"
        : "+f"(d[0]), "+f"(d[1]), "+f"(d[2]), "+f"(d[3])
        : "r"(a0), "r"(a1), "r"(a2), "r"(a3), "r"(b0), "r"(b1));
}
// fp16 hi/lo split of two floats, packed
__device__ __forceinline__ void split2h(float t0, float t1, u32 &wh, u32 &wl) {
    __half h0 = __float2half(t0);
    __half l0 = __float2half(t0 - __half2float(h0));
    __half h1 = __float2half(t1);
    __half l1 = __float2half(t1 - __half2float(h1));
    wh = (u32)__half_as_ushort(h0) | ((u32)__half_as_ushort(h1) << 16);
    wl = (u32)__half_as_ushort(l0) | ((u32)__half_as_ushort(l1) << 16);
}

// ------------------------------------------------------------------
// Probe: no-op launch to shift the fixed ncu capture slot onto mma_main
// ------------------------------------------------------------------
__global__ void probe_kernel() {}

// ------------------------------------------------------------------
// Prepass: Wc[v] = fc2_w[v] @ glu_w[v]^T (fp32), emit fp16 fragment-major.
//          bc[v] = fc2_b[v] @ glu_w[v]^T + glu_b[v]
// ------------------------------------------------------------------
#define PREP_SA    0
#define PREP_SB    66560
#define PREP_F2B   83200
#define PREP_SMEM  83712

__global__ __launch_bounds__(256) void prep_wc(
    const float* __restrict__ fc2_w, const float* __restrict__ fc2_b,
    const float* __restrict__ glu_w, const float* __restrict__ glu_b)
{
    extern __shared__ char smraw[];
    float* sA   = (float*)(smraw + PREP_SA);
    float* sB   = (float*)(smraw + PREP_SB);
    float* sf2b = (float*)(smraw + PREP_F2B);

    const int tid = threadIdx.x;
    const int v   = blockIdx.x;

    for (int i = tid; i < 16384; i += 256) {
        int h = i >> 7, k = i & 127;
        sA[h * 130 + k] = fc2_w[(size_t)v * 16384 + i];
    }
    if (tid < 128) sf2b[tid] = fc2_b[v * NH + tid];
    __syncthreads();

    const int h  = tid & 127;
    const int g0 = (tid >> 7) * 16;

    const int k2    = h >> 1;
    const int hw    = h & 1;
    const int tig   = k2 & 3;
    const int which = (k2 >> 2) & 1;
    const int kk    = k2 >> 3;

    for (int gt = 0; gt < 8; gt++) {
        for (int i = tid; i < 4096; i += 256) {
            int g = i >> 7, k = i & 127;
            sB[g * 130 + k] = glu_w[(size_t)v * 32768 + gt * 4096 + i];
        }
        __syncthreads();

        ull acc[16];
        #pragma unroll
        for (int j = 0; j < 16; j++) acc[j] = 0ull;

        #pragma unroll 4
        for (int kp = 0; kp < 64; kp++) {
            ull a = *(const ull*)(sA + h * 130 + 2 * kp);
            #pragma unroll
            for (int j = 0; j < 16; j++)
                ffma2(acc[j], a, *(const ull*)(sB + (g0 + j) * 130 + 2 * kp));
        }
        #pragma unroll
        for (int j = 0; j < 16; j++) {
            int gabs = gt * 32 + g0 + j;
            float val = upk_sum(acc[j]);
            int halfc = gabs >> 7;
            int rem   = gabs & 127;
            int gg    = rem & 7;
            int s     = rem >> 3;
            int s4    = s >> 2, sj = s & 3;
            int lanec = 4 * gg + tig;
            int bfw   = ((kk * 16 + halfc * 8 + which * 4 + s4) * 128) + lanec * 4 + sj;
            g_bf[(size_t)v * 32768 + (size_t)bfw * 2 + hw] = __float2half(val);
        }
        if (tid < 32) {
            float s = 0.f;
            for (int k = 0; k < 128; k++) s += sf2b[k] * sB[tid * 130 + k];
            g_bc[v * 256 + gt * 32 + tid] = s + glu_b[(size_t)v * 256 + gt * 32 + tid];
        }
        __syncthreads();
    }
}

// ------------------------------------------------------------------
// Kernel 1: weights branch -> softmax wts (unchanged, known-correct)
// ------------------------------------------------------------------
__global__ __launch_bounds__(256) void wts_kernel(
    const float* __restrict__ x,
    const float* __restrict__ wfc1_w, const float* __restrict__ wfc1_b,
    const float* __restrict__ wfc2_w, const float* __restrict__ wfc2_b,
    const float* __restrict__ wglu_w, const float* __restrict__ wglu_b,
    const float* __restrict__ wln_g,  const float* __restrict__ wln_b,
    float* __restrict__ wts_out)
{
    __shared__ float sx[8][NV];
    __shared__ float sa[8][NH];
    __shared__ float sb[8][NH];
    __shared__ float sg[8][2 * NV];

    const int tid = threadIdx.x;
    const int n0  = blockIdx.x * 8;

    for (int i = tid; i < 8 * NV; i += 256) sx[i / NV][i % NV] = x[n0 * NV + i];
    __syncthreads();

    const int h  = tid & 127;
    const int rh = tid >> 7;

    {
        float acc[4];
        float bia = wfc1_b[h];
        #pragma unroll
        for (int i = 0; i < 4; i++) acc[i] = bia;
        for (int v = 0; v < NV; v++) {
            float w = wfc1_w[v * NH + h];
            #pragma unroll
            for (int i = 0; i < 4; i++) acc[i] += sx[rh * 4 + i][v] * w;
        }
        #pragma unroll
        for (int i = 0; i < 4; i++) sa[rh * 4 + i][h] = elu1(acc[i]);
    }
    __syncthreads();

    {
        float acc[4];
        float bia = wfc2_b[h];
        #pragma unroll
        for (int i = 0; i < 4; i++) acc[i] = bia;
        for (int k = 0; k < NH; k++) {
            float w = wfc2_w[k * NH + h];
            #pragma unroll
            for (int i = 0; i < 4; i++) acc[i] += sa[rh * 4 + i][k] * w;
        }
        #pragma unroll
        for (int i = 0; i < 4; i++) sb[rh * 4 + i][h] = acc[i];
    }
    __syncthreads();

    for (int jb = 0; jb < 2 * NV; jb += 256) {
        int j = jb + tid;
        if (j < 2 * NV) {
            float acc[8];
            float bia = wglu_b[j];
            #pragma unroll
            for (int r = 0; r < 8; r++) acc[r] = bia;
            for (int k = 0; k < NH; k++) {
                float w = wglu_w[k * 2 * NV + j];
                #pragma unroll
                for (int r = 0; r < 8; r++) acc[r] += sb[r][k] * w;
            }
            #pragma unroll
            for (int r = 0; r < 8; r++) sg[r][j] = acc[r];
        }
    }
    __syncthreads();

    const int r = tid >> 5, l = tid & 31;
    float y[7];
    #pragma unroll
    for (int p = 0; p < 7; p++) {
        int v = l + 32 * p;
        if (v < NV) {
            float fo  = sg[r][v];
            float gt  = sg[r][v + NV];
            float sig = 1.f / (1.f + expf(-gt));
            y[p] = sx[r][v] + fo * sig;
        } else y[p] = 0.f;
    }
    float s = 0.f;
    #pragma unroll
    for (int p = 0; p < 7; p++) s += y[p];
    float mean = warp_sum(s) * (1.f / (float)NV);

    float s2 = 0.f;
    #pragma unroll
    for (int p = 0; p < 7; p++) {
        int v = l + 32 * p;
        if (v < NV) { float d = y[p] - mean; s2 += d * d; }
    }
    float rs = rsqrtf(warp_sum(s2) * (1.f / (float)NV) + 1e-5f);

    float z[7]; float zmax = -1e30f;
    #pragma unroll
    for (int p = 0; p < 7; p++) {
        int v = l + 32 * p;
        if (v < NV) {
            z[p] = (y[p] - mean) * rs * wln_g[v] + wln_b[v];
            zmax = fmaxf(zmax, z[p]);
        } else z[p] = -1e30f;
    }
    zmax = warp_max(zmax);
    float es = 0.f;
    #pragma unroll
    for (int p = 0; p < 7; p++) {
        int v = l + 32 * p;
        if (v < NV) { z[p] = expf(z[p] - zmax); es += z[p]; }
    }
    float inv = 1.f / warp_sum(es);
    #pragma unroll
    for (int p = 0; p < 7; p++) {
        int v = l + 32 * p;
        if (v < NV) {
            float wt = z[p] * inv;
            wts_out[(n0 + r) * NV + v] = wt;
            g_wtsT[v * NTOK + n0 + r]  = wt;
        }
    }
}

// ------------------------------------------------------------------
// Main kernel: fp16 HMMA 2-term GEMM (A hi+lo, B single fp16),
// fragment-major B (LDS.128), all-warp coalesced epilogue.
// ------------------------------------------------------------------
#define SB_BF   0                  // 65536 B
#define SB_AH   65536              // 64*72*4 = 18432
#define SB_AL   83968              // 18432 -> 102400
#define SB_FCB  65536              // fc preact 64*132*4 = 33792 (overlays AH)
#define SB_GTB  99328              // gate preact 33792 -> 133120 (overlays AL tail)
#define SB_SX   133120
#define SB_SWT  133376
#define SB_F1W  133632
#define SB_F1B  134144
#define SB_SKW  134656
#define SB_SKB  135168
#define SB_LNG  135680
#define SB_LNB  136192
#define SB_BC   136704             // 1024 B -> 137728
#define SB_SMEM 137728

__global__ __launch_bounds__(256, 1) void mma_main(
    const float* __restrict__ x,
    const float* __restrict__ fc1_w, const float* __restrict__ fc1_b,
    const float* __restrict__ skip_w, const float* __restrict__ skip_b,
    const float* __restrict__ ln_g,  const float* __restrict__ ln_b)
{
    extern __shared__ char smraw[];
    u32*   BF   = (u32*)(smraw + SB_BF);
    u32*   AH   = (u32*)(smraw + SB_AH);
    u32*   AL   = (u32*)(smraw + SB_AL);
    float* fcb  = (float*)(smraw + SB_FCB);
    float* gtb  = (float*)(smraw + SB_GTB);
    float* sx   = (float*)(smraw + SB_SX);
    float* swt  = (float*)(smraw + SB_SWT);
    float* sf1w = (float*)(smraw + SB_F1W);
    float* sf1b = (float*)(smraw + SB_F1B);
    float* sskw = (float*)(smraw + SB_SKW);
    float* sskb = (float*)(smraw + SB_SKB);
    float* slng = (float*)(smraw + SB_LNG);
    float* slnb = (float*)(smraw + SB_LNB);
    float* sbc  = (float*)(smraw + SB_BC);

    const int tid  = threadIdx.x;
    const int wid  = tid >> 5;
    const int lane = tid & 31;
    const int g    = lane >> 2;
    const int tig  = lane & 3;
    const int half = wid >> 2;       // 0 = fc cols, 1 = gate cols
    const int w2   = wid & 3;
    const int r0   = 16 * w2;
    const int v    = blockIdx.y;

    // copy fragment-major Wc slab (65536 B)
    {
        const int4* src = (const int4*)(g_bf + (size_t)v * 32768);
        int4* dst = (int4*)BF;
        for (int i = tid; i < 4096; i += 256) dst[i] = src[i];
    }
    if (tid < 128) {
        sf1w[tid] = fc1_w[v * NH + tid];
        sf1b[tid] = fc1_b[v * NH + tid];
        sskw[tid] = skip_w[v * NH + tid];
        sskb[tid] = skip_b[v * NH + tid];
        slng[tid] = ln_g[tid];
        slnb[tid] = ln_b[tid];
    }
    sbc[tid] = g_bc[v * 256 + tid];

    const int arow0 = (r0 + g) * 72;
    const int arow1 = (r0 + g + 8) * 72;

    for (int mi = 0; mi < 8; mi++) {
        const int n0 = (blockIdx.x * 8 + mi) * 64;
        __syncthreads();   // prev epilogue readers done; B copy done (mi=0)

        if (tid < 64) {
            sx[tid]  = x[(size_t)(n0 + tid) * NV + v];
            swt[tid] = g_wtsT[v * NTOK + n0 + tid];
        }
        // A staging: [row][kk][tig][which] with row stride 72, fp16 hi/lo
        for (int idx = tid; idx < 4096; idx += 256) {
            int row = idx >> 6, k2 = idx & 63;
            float xv = x[(size_t)(n0 + row) * NV + v];
            float t0 = elu1f(xv * sf1w[2 * k2]     + sf1b[2 * k2]);
            float t1 = elu1f(xv * sf1w[2 * k2 + 1] + sf1b[2 * k2 + 1]);
            u32 wh, wl;
            split2h(t0, t1, wh, wl);
            int aoff = row * 72 + (k2 >> 3) * 8 + (k2 & 3) * 2 + ((k2 >> 2) & 1);
            AH[aoff] = wh;
            AL[aoff] = wl;
        }
        __syncthreads();

        float acc[16][4];
        #pragma unroll
        for (int s = 0; s < 16; s++)
            #pragma unroll
            for (int j = 0; j < 4; j++) acc[s][j] = 0.f;

        for (int kk = 0; kk < 8; kk++) {
            const int aoff = kk * 8 + tig * 2;
            uint2 xh0 = *(const uint2*)(AH + arow0 + aoff);
            uint2 xh1 = *(const uint2*)(AH + arow1 + aoff);
            uint2 xl0 = *(const uint2*)(AL + arow0 + aoff);
            uint2 xl1 = *(const uint2*)(AL + arow1 + aoff);

            u32 bh[32];
            const u32* pbh = BF + (kk * 16 + half * 8) * 128 + lane * 4;
            #pragma unroll
            for (int q = 0; q < 8; q++)
                *(uint4*)(bh + 4 * q) = *(const uint4*)(pbh + q * 128);

            #pragma unroll
            for (int s = 0; s < 16; s++)
                mma16816h(acc[s], xh0.x, xh1.x, xh0.y, xh1.y, bh[s], bh[16 + s]);
            #pragma unroll
            for (int s = 0; s < 16; s++)
                mma16816h(acc[s], xl0.x, xl1.x, xl0.y, xl1.y, bh[s], bh[16 + s]);
        }
        __syncthreads();   // all MMA reads of AH/AL done before overlay write

        // publish biased preacts (fc warps -> fcb, gate -> gtb)
        {
            float* pre = half ? gtb : fcb;
            const float* bias = sbc + half * 128;
            #pragma unroll
            for (int s = 0; s < 16; s++)
                #pragma unroll
                for (int j = 0; j < 4; j++) {
                    int cg  = 8 * s + 2 * tig + (j & 1);
                    int row = r0 + g + 8 * (j >> 1);
                    pre[row * 132 + cg] = acc[s][j] + bias[cg];
                }
        }
        __syncthreads();

        // all-warp epilogue: warp w handles rows 8w..8w+7
        {
            float lngv0 = slng[4 * lane],     lngv1 = slng[4 * lane + 1];
            float lngv2 = slng[4 * lane + 2], lngv3 = slng[4 * lane + 3];
            float lnbv0 = slnb[4 * lane],     lnbv1 = slnb[4 * lane + 1];
            float lnbv2 = slnb[4 * lane + 2], lnbv3 = slnb[4 * lane + 3];
            float skw0 = sskw[4 * lane],     skw1 = sskw[4 * lane + 1];
            float skw2 = sskw[4 * lane + 2], skw3 = sskw[4 * lane + 3];
            float skb0 = sskb[4 * lane],     skb1 = sskb[4 * lane + 1];
            float skb2 = sskb[4 * lane + 2], skb3 = sskb[4 * lane + 3];

            #pragma unroll
            for (int rr = 0; rr < 8; rr++) {
                int row = 8 * wid + rr;
                float4 f  = *(const float4*)(fcb + row * 132 + 4 * lane);
                float4 gt = *(const float4*)(gtb + row * 132 + 4 * lane);
                float xv  = sx[row];
                float wt  = swt[row];
                float val0 = f.x * (1.f / (1.f + __expf(-gt.x))) + xv * skw0 + skb0;
                float val1 = f.y * (1.f / (1.f + __expf(-gt.y))) + xv * skw1 + skb1;
                float val2 = f.z * (1.f / (1.f + __expf(-gt.z))) + xv * skw2 + skb2;
                float val3 = f.w * (1.f / (1.f + __expf(-gt.w))) + xv * skw3 + skb3;
                float mean = warp_sum(val0 + val1 + val2 + val3) * (1.f / 128.f);
                float d0 = val0 - mean, d1 = val1 - mean, d2 = val2 - mean, d3 = val3 - mean;
                float rs = rsqrtf(warp_sum(d0 * d0 + d1 * d1 + d2 * d2 + d3 * d3) * (1.f / 128.f) + 1e-5f);
                float4 o;
                o.x = wt * (d0 * rs * lngv0 + lnbv0);
                o.y = wt * (d1 * rs * lngv1 + lnbv1);
                o.z = wt * (d2 * rs * lngv2 + lnbv2);
                o.w = wt * (d3 * rs * lngv3 + lnbv3);
                *(float4*)(g_vpart + (size_t)v * ((size_t)NTOK * NH)
                           + (size_t)(n0 + row) * NH + 4 * lane) = o;
            }
        }
    }
}

// ------------------------------------------------------------------
// Reduce: sum 204 per-variable partials -> out
// ------------------------------------------------------------------
__global__ __launch_bounds__(256) void reduce_kernel(float* __restrict__ out)
{
    int i = blockIdx.x * 256 + threadIdx.x;
    const float* p = g_vpart + i;
    float s = 0.f;
    #pragma unroll 4
    for (int v = 0; v < NV; v++) s += p[(size_t)v * ((size_t)NTOK * NH)];
    out[i] = s;
}

// ------------------------------------------------------------------
extern "C" void kernel_launch(void* const* d_in, const int* in_sizes, int n_in,
                              void* d_out, int out_size) {
    const float* x      = (const float*)d_in[0];
    const float* fc1_w  = (const float*)d_in[1];
    const float* fc1_b  = (const float*)d_in[2];
    const float* fc2_w  = (const float*)d_in[3];
    const float* fc2_b  = (const float*)d_in[4];
    const float* glu_w  = (const float*)d_in[5];
    const float* glu_b  = (const float*)d_in[6];
    const float* skip_w = (const float*)d_in[7];
    const float* skip_b = (const float*)d_in[8];
    const float* ln_g   = (const float*)d_in[9];
    const float* ln_b   = (const float*)d_in[10];
    const float* wfc1_w = (const float*)d_in[11];
    const float* wfc1_b = (const float*)d_in[12];
    const float* wfc2_w = (const float*)d_in[13];
    const float* wfc2_b = (const float*)d_in[14];
    const float* wglu_w = (const float*)d_in[15];
    const float* wglu_b = (const float*)d_in[16];
    const float* wln_g  = (const float*)d_in[17];
    const float* wln_b  = (const float*)d_in[18];

    float* out = (float*)d_out;
    float* wts = out + (size_t)NTOK * NH;

    cudaFuncSetAttribute(prep_wc,  cudaFuncAttributeMaxDynamicSharedMemorySize, PREP_SMEM);
    cudaFuncSetAttribute(mma_main, cudaFuncAttributeMaxDynamicSharedMemorySize, SB_SMEM);

    probe_kernel<<<1, 32>>>();   // shifts ncu capture slot onto mma_main
    prep_wc<<<NV, 256, PREP_SMEM>>>(fc2_w, fc2_b, glu_w, glu_b);
    wts_kernel<<<NTOK / 8, 256>>>(x, wfc1_w, wfc1_b, wfc2_w, wfc2_b,
                                  wglu_w, wglu_b, wln_g, wln_b, wts);
    mma_main<<<dim3(8, NV), 256, SB_SMEM>>>(
        x, fc1_w, fc1_b, skip_w, skip_b, ln_g, ln_b);
    reduce_kernel<<<(NTOK * NH) / 256, 256>>>(out);
}